// round 6
// baseline (speedup 1.0000x reference)
#include <cuda_runtime.h>

// ---------------- problem constants (fixed shapes) ----------------
#define N_SRC1 200000
#define N_DST1 50000
#define N_DST2 10000
#define E1     2000000
#define E2     400000
#define IN_F   128
#define H_F    256
#define N_CLS  47

#define PAD1   50048   // N_DST1 padded to multiple of 64
#define PAD2   10048

// ---------------- scratch (device globals; zero-initialized) ----------------
__device__ int   g_is64;
__device__ int   g_src1[E1];
__device__ int   g_src2[E2];
__device__ int   g_off1[N_DST1 + 1];
__device__ int   g_off2[N_DST2 + 1];
__device__ float g_h[(size_t)PAD1 * H_F];          // layer1 output (relu'd)
__device__ float g_hneigh2[(size_t)PAD2 * H_F];    // layer2 mean-aggregated feats

// ---------------- index dtype detection ----------------
// src1 values are uniform-random in [0, 200000). If the array is int64, every
// odd 32-bit word (the high word) is zero. If int32, odd words are random and
// essentially surely nonzero among 128 samples.
__global__ void detect_kernel(const int* __restrict__ src1_raw) {
    if (threadIdx.x == 0) {
        int nz = 0;
        for (int i = 1; i < 256; i += 2) nz |= (src1_raw[i] != 0);
        g_is64 = nz ? 0 : 1;
    }
}

__global__ void convert1_kernel(const void* __restrict__ src) {
    int i = blockIdx.x * blockDim.x + threadIdx.x;
    if (i >= E1) return;
    if (g_is64) g_src1[i] = (int)((const long long*)src)[i];
    else        g_src1[i] = ((const int*)src)[i];
}
__global__ void convert2_kernel(const void* __restrict__ src) {
    int i = blockIdx.x * blockDim.x + threadIdx.x;
    if (i >= E2) return;
    if (g_is64) g_src2[i] = (int)((const long long*)src)[i];
    else        g_src2[i] = ((const int*)src)[i];
}

// ---------------- CSR offsets from sorted dst via boundary scatter ----------------
// off[t] = lower_bound(dst, t). Thread i owns all t with dst[i-1] < t <= dst[i].
__global__ void offsets_kernel(const void* __restrict__ dst, int* __restrict__ off,
                               int E, int ndst) {
    int i = blockIdx.x * blockDim.x + threadIdx.x;
    if (i >= E) return;
    int d, p;
    if (g_is64) {
        d = (int)((const long long*)dst)[i];
        p = (i == 0) ? -1 : (int)((const long long*)dst)[i - 1];
    } else {
        d = ((const int*)dst)[i];
        p = (i == 0) ? -1 : ((const int*)dst)[i - 1];
    }
    for (int t = p + 1; t <= d; ++t) off[t] = i;
    if (i == E - 1)
        for (int t = d + 1; t <= ndst; ++t) off[t] = E;
}

// ---------------- fused layer-1: aggregation + dual-GEMM + bias + relu ----------------
// Per block: 64 dst rows (BM=64), full N=256 (BN=256). Aggregated neighbor
// feats live in a resident smem tile; self A-tiles and B-tiles are
// double-buffered. Even blocks do AGG first, odd blocks do the (independent)
// self-GEMM first, so memory and fma pipes overlap chip-wide.
#define LDH 132    // sHn row stride (floats): 132 mod 32 = 4 -> conflict-free reads
#define LDA 20     // sA row stride

__device__ __forceinline__ void agg_phase(float* __restrict__ sHn,
                                          const float* __restrict__ x,
                                          int bm, int tid) {
    int warp = tid >> 5, lane = tid & 31;
    #pragma unroll 1
    for (int r = 0; r < 8; ++r) {
        int local = warp * 8 + r;
        int grow  = bm + local;
        float ax = 0.f, ay = 0.f, az = 0.f, aw = 0.f;
        if (grow < N_DST1) {
            int s = g_off1[grow], e = g_off1[grow + 1];
            int i = s;
            for (; i + 4 <= e; i += 4) {           // 4 gathers in flight
                int s0 = g_src1[i], s1 = g_src1[i+1], s2 = g_src1[i+2], s3 = g_src1[i+3];
                float4 v0 = __ldg((const float4*)(x + (size_t)s0 * IN_F) + lane);
                float4 v1 = __ldg((const float4*)(x + (size_t)s1 * IN_F) + lane);
                float4 v2 = __ldg((const float4*)(x + (size_t)s2 * IN_F) + lane);
                float4 v3 = __ldg((const float4*)(x + (size_t)s3 * IN_F) + lane);
                ax += (v0.x + v1.x) + (v2.x + v3.x);
                ay += (v0.y + v1.y) + (v2.y + v3.y);
                az += (v0.z + v1.z) + (v2.z + v3.z);
                aw += (v0.w + v1.w) + (v2.w + v3.w);
            }
            for (; i < e; ++i) {
                int s0 = g_src1[i];
                float4 v0 = __ldg((const float4*)(x + (size_t)s0 * IN_F) + lane);
                ax += v0.x; ay += v0.y; az += v0.z; aw += v0.w;
            }
            int deg = e - s;
            float sc = 1.0f / (float)(deg > 0 ? deg : 1);
            ax *= sc; ay *= sc; az *= sc; aw *= sc;
        }
        *(float4*)&sHn[local * LDH + lane * 4] = make_float4(ax, ay, az, aw);
    }
    __syncthreads();
}

__global__ __launch_bounds__(256, 2) void fused1_kernel(
    const float* __restrict__ x, const float* __restrict__ Wself,
    const float* __restrict__ Wneigh, const float* __restrict__ bias1) {
    extern __shared__ float sm[];
    float* sHn = sm;                       // [64][LDH]
    float* sA  = sm + 64 * LDH;            // [2][64][LDA]
    float* sB  = sA + 2 * 64 * LDA;        // [2][16][256]

    int tid = threadIdx.x;
    int tx  = tid & 15;                    // n-group: cols tx*16 .. tx*16+15
    int ty  = tid >> 4;                    // m-group: rows ty*4 .. ty*4+3
    int bm  = blockIdx.x * 64;
    bool aggFirst = (blockIdx.x & 1) == 0;

    unsigned long long acc[4][8];
    #pragma unroll
    for (int i = 0; i < 4; i++)
        #pragma unroll
        for (int j = 0; j < 8; j++) acc[i][j] = 0ULL;

    if (aggFirst) agg_phase(sHn, x, bm, tid);

    // ---- SELF GEMM: k = 0..127, A = x rows bm..bm+63, B = Wself ----
    {
        int arow = tid >> 2, acg = (tid & 3) * 4;
        int brow = tid >> 4;
        // prologue: chunk 0 -> buf 0
        {
            float4 av = *(const float4*)(x + (size_t)(bm + arow) * IN_F + acg);
            *(float4*)&sA[arow * LDA + acg] = av;
            const float4* wp = (const float4*)(Wself + (size_t)brow * H_F + tx * 16);
            float4 b0 = wp[0], b1 = wp[1], b2 = wp[2], b3 = wp[3];
            float4* sp = (float4*)&sB[brow * 256 + tx * 16];
            sp[0] = b0; sp[1] = b1; sp[2] = b2; sp[3] = b3;
        }
        __syncthreads();
        #pragma unroll 1
        for (int c = 0; c < 8; ++c) {
            int buf = c & 1;
            float4 pav, pb0, pb1, pb2, pb3;
            if (c < 7) {
                int k0 = (c + 1) * 16;
                pav = *(const float4*)(x + (size_t)(bm + arow) * IN_F + k0 + acg);
                const float4* wp = (const float4*)(Wself + (size_t)(k0 + brow) * H_F + tx * 16);
                pb0 = wp[0]; pb1 = wp[1]; pb2 = wp[2]; pb3 = wp[3];
            }
            const float* A  = sA + buf * 64 * LDA;
            const float* Bp = sB + buf * 16 * 256;
            #pragma unroll
            for (int k = 0; k < 16; ++k) {
                float av4[4];
                av4[0] = A[(ty * 4 + 0) * LDA + k];
                av4[1] = A[(ty * 4 + 1) * LDA + k];
                av4[2] = A[(ty * 4 + 2) * LDA + k];
                av4[3] = A[(ty * 4 + 3) * LDA + k];
                const ulonglong2* bq = (const ulonglong2*)&Bp[k * 256 + tx * 16];
                ulonglong2 q0 = bq[0], q1 = bq[1], q2 = bq[2], q3 = bq[3];
                unsigned long long bb[8] = {q0.x, q0.y, q1.x, q1.y, q2.x, q2.y, q3.x, q3.y};
                #pragma unroll
                for (int i = 0; i < 4; i++) {
                    unsigned long long ad;
                    asm("mov.b64 %0, {%1, %1};" : "=l"(ad) : "f"(av4[i]));
                    #pragma unroll
                    for (int j = 0; j < 8; j++)
                        asm("fma.rn.f32x2 %0, %1, %2, %0;"
                            : "+l"(acc[i][j]) : "l"(ad), "l"(bb[j]));
                }
            }
            if (c < 7) {
                __syncthreads();
                *(float4*)&sA[(buf ^ 1) * 64 * LDA + arow * LDA + acg] = pav;
                float4* sp = (float4*)&sB[(buf ^ 1) * 16 * 256 + brow * 256 + tx * 16];
                sp[0] = pb0; sp[1] = pb1; sp[2] = pb2; sp[3] = pb3;
                __syncthreads();
            }
        }
    }

    if (!aggFirst) agg_phase(sHn, x, bm, tid);

    // ---- NEIGH GEMM: k = 0..127, A = sHn (resident), B = Wneigh ----
    __syncthreads();   // protect sB overwrite vs self-gemm readers (aggFirst path)
    {
        int brow = tid >> 4;
        {
            const float4* wp = (const float4*)(Wneigh + (size_t)brow * H_F + tx * 16);
            float4 b0 = wp[0], b1 = wp[1], b2 = wp[2], b3 = wp[3];
            float4* sp = (float4*)&sB[brow * 256 + tx * 16];
            sp[0] = b0; sp[1] = b1; sp[2] = b2; sp[3] = b3;
        }
        __syncthreads();
        #pragma unroll 1
        for (int c = 0; c < 8; ++c) {
            int buf = c & 1;
            float4 pb0, pb1, pb2, pb3;
            if (c < 7) {
                int k0 = (c + 1) * 16;
                const float4* wp = (const float4*)(Wneigh + (size_t)(k0 + brow) * H_F + tx * 16);
                pb0 = wp[0]; pb1 = wp[1]; pb2 = wp[2]; pb3 = wp[3];
            }
            const float* Bp = sB + buf * 16 * 256;
            #pragma unroll
            for (int k = 0; k < 16; ++k) {
                int kg = c * 16 + k;
                float av4[4];
                av4[0] = sHn[(ty * 4 + 0) * LDH + kg];
                av4[1] = sHn[(ty * 4 + 1) * LDH + kg];
                av4[2] = sHn[(ty * 4 + 2) * LDH + kg];
                av4[3] = sHn[(ty * 4 + 3) * LDH + kg];
                const ulonglong2* bq = (const ulonglong2*)&Bp[k * 256 + tx * 16];
                ulonglong2 q0 = bq[0], q1 = bq[1], q2 = bq[2], q3 = bq[3];
                unsigned long long bb[8] = {q0.x, q0.y, q1.x, q1.y, q2.x, q2.y, q3.x, q3.y};
                #pragma unroll
                for (int i = 0; i < 4; i++) {
                    unsigned long long ad;
                    asm("mov.b64 %0, {%1, %1};" : "=l"(ad) : "f"(av4[i]));
                    #pragma unroll
                    for (int j = 0; j < 8; j++)
                        asm("fma.rn.f32x2 %0, %1, %2, %0;"
                            : "+l"(acc[i][j]) : "l"(ad), "l"(bb[j]));
                }
            }
            if (c < 7) {
                __syncthreads();
                float4* sp = (float4*)&sB[(buf ^ 1) * 16 * 256 + brow * 256 + tx * 16];
                sp[0] = pb0; sp[1] = pb1; sp[2] = pb2; sp[3] = pb3;
                __syncthreads();
            }
        }
    }

    // ---- epilogue: bias + relu -> g_h ----
    const float4* bp = (const float4*)(bias1 + tx * 16);
    float4 bb0 = bp[0], bb1 = bp[1], bb2 = bp[2], bb3 = bp[3];
    float bv[16] = {bb0.x, bb0.y, bb0.z, bb0.w, bb1.x, bb1.y, bb1.z, bb1.w,
                    bb2.x, bb2.y, bb2.z, bb2.w, bb3.x, bb3.y, bb3.z, bb3.w};
    #pragma unroll
    for (int i = 0; i < 4; i++) {
        int m = bm + ty * 4 + i;          // < PAD1 always
        float v[16];
        #pragma unroll
        for (int j = 0; j < 8; j++) {
            float lo, hi;
            asm("mov.b64 {%0, %1}, %2;" : "=f"(lo), "=f"(hi) : "l"(acc[i][j]));
            v[2 * j]     = lo;
            v[2 * j + 1] = hi;
        }
        float* op = g_h + (size_t)m * H_F + tx * 16;
        #pragma unroll
        for (int q = 0; q < 4; q++) {
            float4 r;
            r.x = fmaxf(v[4*q+0] + bv[4*q+0], 0.f);
            r.y = fmaxf(v[4*q+1] + bv[4*q+1], 0.f);
            r.z = fmaxf(v[4*q+2] + bv[4*q+2], 0.f);
            r.w = fmaxf(v[4*q+3] + bv[4*q+3], 0.f);
            *(float4*)(op + 4 * q) = r;
        }
    }
}

// ---------------- layer-2 aggregation: one warp per dst, 256 feats ----------------
__global__ __launch_bounds__(256) void agg2_kernel() {
    int gw   = (blockIdx.x * 256 + threadIdx.x) >> 5;
    if (gw >= N_DST2) return;
    int lane = threadIdx.x & 31;
    int s = g_off2[gw], e = g_off2[gw + 1];
    float4 a0 = make_float4(0.f, 0.f, 0.f, 0.f);
    float4 a1 = make_float4(0.f, 0.f, 0.f, 0.f);
    int i = s;
    for (; i + 4 <= e; i += 4) {
        int s0 = g_src2[i], s1 = g_src2[i + 1], s2 = g_src2[i + 2], s3 = g_src2[i + 3];
        const float4* r0 = (const float4*)(g_h + (size_t)s0 * H_F);
        const float4* r1 = (const float4*)(g_h + (size_t)s1 * H_F);
        const float4* r2 = (const float4*)(g_h + (size_t)s2 * H_F);
        const float4* r3 = (const float4*)(g_h + (size_t)s3 * H_F);
        float4 u0 = r0[lane], u1 = r0[lane + 32];
        float4 w0 = r1[lane], w1 = r1[lane + 32];
        float4 p0 = r2[lane], p1 = r2[lane + 32];
        float4 q0 = r3[lane], q1 = r3[lane + 32];
        a0.x += (u0.x + w0.x) + (p0.x + q0.x); a0.y += (u0.y + w0.y) + (p0.y + q0.y);
        a0.z += (u0.z + w0.z) + (p0.z + q0.z); a0.w += (u0.w + w0.w) + (p0.w + q0.w);
        a1.x += (u1.x + w1.x) + (p1.x + q1.x); a1.y += (u1.y + w1.y) + (p1.y + q1.y);
        a1.z += (u1.z + w1.z) + (p1.z + q1.z); a1.w += (u1.w + w1.w) + (p1.w + q1.w);
    }
    for (; i < e; ++i) {
        int s0 = g_src2[i];
        const float4* r0 = (const float4*)(g_h + (size_t)s0 * H_F);
        float4 u0 = r0[lane], u1 = r0[lane + 32];
        a0.x += u0.x; a0.y += u0.y; a0.z += u0.z; a0.w += u0.w;
        a1.x += u1.x; a1.y += u1.y; a1.z += u1.z; a1.w += u1.w;
    }
    int deg = e - s;
    float sc = 1.0f / (float)(deg > 0 ? deg : 1);
    float4* op = (float4*)(g_hneigh2 + (size_t)gw * H_F);
    op[lane]      = make_float4(a0.x * sc, a0.y * sc, a0.z * sc, a0.w * sc);
    op[lane + 32] = make_float4(a1.x * sc, a1.y * sc, a1.z * sc, a1.w * sc);
}

// ---------------- layer-2 fused dual-GEMM + bias (no relu) ----------------
__global__ __launch_bounds__(256) void gemm2_kernel(
    const float* __restrict__ Ws2, const float* __restrict__ Wn2,
    const float* __restrict__ b2, float* __restrict__ out) {
    __shared__ float sWs[64][48];
    __shared__ float sWn[64][48];
    __shared__ float sAS[32][64];
    __shared__ float sAN[32][64];

    int t    = threadIdx.x;
    int n    = t & 63;
    int rg   = t >> 6;                      // 0..3
    int nc   = (n < N_CLS) ? n : (N_CLS - 1);
    int row0 = blockIdx.x * 32;

    float acc[8];
    #pragma unroll
    for (int i = 0; i < 8; i++) acc[i] = 0.f;

    for (int kt = 0; kt < 4; ++kt) {
        for (int idx = t; idx < 64 * N_CLS; idx += 256) {
            int kk = idx / N_CLS;
            int nn = idx - kk * N_CLS;
            sWs[kk][nn] = Ws2[(kt * 64 + kk) * N_CLS + nn];
            sWn[kk][nn] = Wn2[(kt * 64 + kk) * N_CLS + nn];
        }
        for (int idx = t; idx < 512; idx += 256) {
            int r = idx >> 4;
            int c = (idx & 15) * 4;
            *(float4*)&sAS[r][c] =
                *(const float4*)(g_h + (size_t)(row0 + r) * H_F + kt * 64 + c);
            *(float4*)&sAN[r][c] =
                *(const float4*)(g_hneigh2 + (size_t)(row0 + r) * H_F + kt * 64 + c);
        }
        __syncthreads();
        #pragma unroll 4
        for (int kk = 0; kk < 64; kk++) {
            float ws = sWs[kk][nc];
            float wn = sWn[kk][nc];
            #pragma unroll
            for (int i = 0; i < 8; i++) {
                acc[i] = fmaf(sAS[rg * 8 + i][kk], ws, acc[i]);
                acc[i] = fmaf(sAN[rg * 8 + i][kk], wn, acc[i]);
            }
        }
        __syncthreads();
    }

    if (n < N_CLS) {
        float bb = b2[n];
        #pragma unroll
        for (int i = 0; i < 8; i++) {
            int row = row0 + rg * 8 + i;
            if (row < N_DST2) out[row * N_CLS + n] = acc[i] + bb;
        }
    }
}

// ---------------- launch ----------------
extern "C" void kernel_launch(void* const* d_in, const int* in_sizes, int n_in,
                              void* d_out, int out_size) {
    const float* x       = (const float*)d_in[0];
    const float* Wself1  = (const float*)d_in[1];
    const float* Wneigh1 = (const float*)d_in[2];
    const float* b1      = (const float*)d_in[3];
    const float* Wself2  = (const float*)d_in[4];
    const float* Wneigh2 = (const float*)d_in[5];
    const float* b2      = (const float*)d_in[6];
    const void*  src1    = d_in[7];
    const void*  dst1    = d_in[8];
    const void*  src2    = d_in[9];
    const void*  dst2    = d_in[10];
    float* out = (float*)d_out;

    int* off1; int* off2;
    cudaGetSymbolAddress((void**)&off1, g_off1);
    cudaGetSymbolAddress((void**)&off2, g_off2);

    const int FUSED1_SMEM = (64 * LDH + 2 * 64 * LDA + 2 * 16 * 256) * 4; // 76800 B
    cudaFuncSetAttribute(fused1_kernel,
                         cudaFuncAttributeMaxDynamicSharedMemorySize, FUSED1_SMEM);

    detect_kernel<<<1, 32>>>((const int*)src1);
    convert1_kernel<<<(E1 + 255) / 256, 256>>>(src1);
    convert2_kernel<<<(E2 + 255) / 256, 256>>>(src2);
    offsets_kernel<<<(E1 + 255) / 256, 256>>>(dst1, off1, E1, N_DST1);
    offsets_kernel<<<(E2 + 255) / 256, 256>>>(dst2, off2, E2, N_DST2);

    fused1_kernel<<<PAD1 / 64, 256, FUSED1_SMEM>>>(x, Wself1, Wneigh1, b1);

    agg2_kernel<<<(N_DST2 + 7) / 8, 256>>>();

    gemm2_kernel<<<(N_DST2 + 31) / 32, 256>>>(Wself2, Wneigh2, b2, out);
}

// round 7
// speedup vs baseline: 1.5991x; 1.5991x over previous
#include <cuda_runtime.h>

// ---------------- problem constants (fixed shapes) ----------------
#define N_SRC1 200000
#define N_DST1 50000
#define N_DST2 10000
#define E1     2000000
#define E2     400000
#define IN_F   128
#define H_F    256
#define N_CLS  47

#define PAD1   50048   // N_DST1 padded to multiple of 128
#define PAD2   10048

#define G_GEMM1 782    // (PAD1/128) * (H_F/128) = 391*2
#define G_AGG1  6250   // N_DST1 / 8 warps
#define SMS     152

// ---------------- scratch (device globals; zero-initialized) ----------------
__device__ int   g_is64;
__device__ float g_hself[(size_t)PAD1 * H_F];      // x @ Wself (raw)
__device__ float g_hneigh1[(size_t)PAD1 * IN_F];   // layer1 mean-aggregated feats
__device__ float g_h[(size_t)PAD1 * H_F];          // layer1 output (relu'd)
__device__ float g_hneigh2[(size_t)PAD2 * H_F];    // layer2 mean-aggregated feats

// ---------------- index dtype detection ----------------
// src1 values are uniform-random in [0, 200000). If int64, every odd 32-bit
// word (high word) is zero; if int32, odd words are random and essentially
// surely nonzero among 128 samples.
__global__ void detect_kernel(const int* __restrict__ src1_raw) {
    if (threadIdx.x == 0) {
        int nz = 0;
        for (int i = 1; i < 256; i += 2) nz |= (src1_raw[i] != 0);
        g_is64 = nz ? 0 : 1;
    }
}

// ---------------- dual interleaved lower_bound (independent chains) ----------------
template <typename IT>
__device__ __forceinline__ void lb2(const IT* __restrict__ a, int n, int k1, int k2,
                                    int& r1, int& r2) {
    int lo1 = 0, hi1 = n, lo2 = 0, hi2 = n;
    while (lo1 < hi1 || lo2 < hi2) {
        int m1 = (lo1 + hi1) >> 1;
        int m2 = (lo2 + hi2) >> 1;
        int v1 = 0, v2 = 0;
        if (lo1 < hi1) v1 = (int)__ldg(a + m1);
        if (lo2 < hi2) v2 = (int)__ldg(a + m2);
        if (lo1 < hi1) { if (v1 < k1) lo1 = m1 + 1; else hi1 = m1; }
        if (lo2 < hi2) { if (v2 < k2) lo2 = m2 + 1; else hi2 = m2; }
    }
    r1 = lo1; r2 = lo2;
}

// ---------------- layer-1 aggregation: one warp per dst row ----------------
template <typename IT>
__device__ __forceinline__ void agg1_warp(const float* __restrict__ x,
                                          const IT* __restrict__ src,
                                          const IT* __restrict__ dst,
                                          int row, int lane) {
    int s, e;
    lb2(dst, E1, row, row + 1, s, e);
    float ax = 0.f, ay = 0.f, az = 0.f, aw = 0.f;
    int i = s;
    for (; i + 4 <= e; i += 4) {            // 4 gathers in flight
        int s0 = (int)__ldg(src + i),     s1 = (int)__ldg(src + i + 1);
        int s2 = (int)__ldg(src + i + 2), s3 = (int)__ldg(src + i + 3);
        float4 v0 = __ldg((const float4*)(x + (size_t)s0 * IN_F) + lane);
        float4 v1 = __ldg((const float4*)(x + (size_t)s1 * IN_F) + lane);
        float4 v2 = __ldg((const float4*)(x + (size_t)s2 * IN_F) + lane);
        float4 v3 = __ldg((const float4*)(x + (size_t)s3 * IN_F) + lane);
        ax += (v0.x + v1.x) + (v2.x + v3.x);
        ay += (v0.y + v1.y) + (v2.y + v3.y);
        az += (v0.z + v1.z) + (v2.z + v3.z);
        aw += (v0.w + v1.w) + (v2.w + v3.w);
    }
    for (; i < e; ++i) {
        int s0 = (int)__ldg(src + i);
        float4 v0 = __ldg((const float4*)(x + (size_t)s0 * IN_F) + lane);
        ax += v0.x; ay += v0.y; az += v0.z; aw += v0.w;
    }
    int deg = e - s;
    float sc = 1.0f / (float)(deg > 0 ? deg : 1);
    ((float4*)(g_hneigh1 + (size_t)row * IN_F))[lane] =
        make_float4(ax * sc, ay * sc, az * sc, aw * sc);
}

// ---------------- shared GEMM body: [PAD1,128] @ [128,256], BM=128 BN=128 BK=16 ----------------
// MODE 0: store raw accumulators to g_hself.
// MODE 1: out = relu(acc + g_hself + bias) -> g_h.
// Double-buffered smem; inner product on packed fma.rn.f32x2.
#define SM_FLOATS (2 * 16 * 136 + 2 * 16 * 128)   // 8448 floats = 33792 B

template <int MODE>
__device__ __forceinline__ void gemm1_body(const float* __restrict__ A,
                                           const float* __restrict__ W,
                                           const float* __restrict__ bias1,
                                           int gidx, float* sm) {
    float* As = sm;                     // [2][16][136] transposed A tiles
    float* Bs = sm + 2 * 16 * 136;      // [2][16][128]

    const int bm = (gidx >> 1) * 128;
    const int bn = (gidx & 1) * 128;
    const int tid = threadIdx.x;
    const int tx = tid & 15;            // cols bn + tx*8 .. +7
    const int ty = tid >> 4;            // rows bm + ty*8 .. +7
    const int ar = tid >> 1;            // A tile row 0..127
    const int akc = (tid & 1) * 8;      // A k-offset 0 or 8
    const int brow = tid >> 4;          // B k-row 0..15
    const int bnc = (tid & 15) * 8;     // B n-offset

    unsigned long long acc[8][4];
    #pragma unroll
    for (int i = 0; i < 8; i++)
        #pragma unroll
        for (int j = 0; j < 4; j++) acc[i][j] = 0ULL;

    const float* aRow = A + (size_t)(bm + ar) * IN_F + akc;
    const float* wRow = W + (size_t)brow * H_F + bn + bnc;

    // prologue: chunk 0 -> buf 0
    {
        float4 a0 = *(const float4*)aRow;
        float4 a1 = *(const float4*)(aRow + 4);
        float4 b0 = *(const float4*)wRow;
        float4 b1 = *(const float4*)(wRow + 4);
        As[(akc + 0) * 136 + ar] = a0.x; As[(akc + 1) * 136 + ar] = a0.y;
        As[(akc + 2) * 136 + ar] = a0.z; As[(akc + 3) * 136 + ar] = a0.w;
        As[(akc + 4) * 136 + ar] = a1.x; As[(akc + 5) * 136 + ar] = a1.y;
        As[(akc + 6) * 136 + ar] = a1.z; As[(akc + 7) * 136 + ar] = a1.w;
        float4* bd = (float4*)(Bs + brow * 128 + bnc);
        bd[0] = b0; bd[1] = b1;
    }
    __syncthreads();

    #pragma unroll 1
    for (int ch = 0; ch < 8; ++ch) {
        int buf = ch & 1;
        float4 pa0, pa1, pb0, pb1;
        if (ch < 7) {
            pa0 = *(const float4*)(aRow + (ch + 1) * 16);
            pa1 = *(const float4*)(aRow + (ch + 1) * 16 + 4);
            pb0 = *(const float4*)(wRow + (size_t)(ch + 1) * 16 * H_F);
            pb1 = *(const float4*)(wRow + (size_t)(ch + 1) * 16 * H_F + 4);
        }
        const float* Ab = As + buf * (16 * 136);
        const float* Bb = Bs + buf * (16 * 128);
        #pragma unroll
        for (int k = 0; k < 16; ++k) {
            float av[8];
            #pragma unroll
            for (int i = 0; i < 8; i++) av[i] = Ab[k * 136 + ty * 8 + i];
            const ulonglong2* bq = (const ulonglong2*)(Bb + k * 128 + tx * 8);
            ulonglong2 q0 = bq[0], q1 = bq[1];
            unsigned long long bb[4] = {q0.x, q0.y, q1.x, q1.y};
            #pragma unroll
            for (int i = 0; i < 8; i++) {
                unsigned long long ad;
                asm("mov.b64 %0, {%1, %1};" : "=l"(ad) : "f"(av[i]));
                #pragma unroll
                for (int j = 0; j < 4; j++)
                    asm("fma.rn.f32x2 %0, %1, %2, %0;"
                        : "+l"(acc[i][j]) : "l"(ad), "l"(bb[j]));
            }
        }
        if (ch < 7) {
            __syncthreads();
            int nb = buf ^ 1;
            float* Ad = As + nb * (16 * 136);
            Ad[(akc + 0) * 136 + ar] = pa0.x; Ad[(akc + 1) * 136 + ar] = pa0.y;
            Ad[(akc + 2) * 136 + ar] = pa0.z; Ad[(akc + 3) * 136 + ar] = pa0.w;
            Ad[(akc + 4) * 136 + ar] = pa1.x; Ad[(akc + 5) * 136 + ar] = pa1.y;
            Ad[(akc + 6) * 136 + ar] = pa1.z; Ad[(akc + 7) * 136 + ar] = pa1.w;
            float4* bd = (float4*)(Bs + nb * (16 * 128) + brow * 128 + bnc);
            bd[0] = pb0; bd[1] = pb1;
            __syncthreads();
        }
    }

    // epilogue
    if (MODE == 0) {
        #pragma unroll
        for (int i = 0; i < 8; i++) {
            int m = bm + ty * 8 + i;
            float v[8];
            #pragma unroll
            for (int j = 0; j < 4; j++) {
                float lo, hi;
                asm("mov.b64 {%0, %1}, %2;" : "=f"(lo), "=f"(hi) : "l"(acc[i][j]));
                v[2 * j] = lo; v[2 * j + 1] = hi;
            }
            float* op = g_hself + (size_t)m * H_F + bn + tx * 8;
            *(float4*)op       = make_float4(v[0], v[1], v[2], v[3]);
            *(float4*)(op + 4) = make_float4(v[4], v[5], v[6], v[7]);
        }
    } else {
        float4 bb0 = *(const float4*)(bias1 + bn + tx * 8);
        float4 bb1 = *(const float4*)(bias1 + bn + tx * 8 + 4);
        #pragma unroll
        for (int i = 0; i < 8; i++) {
            int m = bm + ty * 8 + i;
            const float* hp = g_hself + (size_t)m * H_F + bn + tx * 8;
            float4 h0 = *(const float4*)hp;
            float4 h1 = *(const float4*)(hp + 4);
            float v[8];
            #pragma unroll
            for (int j = 0; j < 4; j++) {
                float lo, hi;
                asm("mov.b64 {%0, %1}, %2;" : "=f"(lo), "=f"(hi) : "l"(acc[i][j]));
                v[2 * j] = lo; v[2 * j + 1] = hi;
            }
            float4 r0, r1;
            r0.x = fmaxf(v[0] + h0.x + bb0.x, 0.f);
            r0.y = fmaxf(v[1] + h0.y + bb0.y, 0.f);
            r0.z = fmaxf(v[2] + h0.z + bb0.z, 0.f);
            r0.w = fmaxf(v[3] + h0.w + bb0.w, 0.f);
            r1.x = fmaxf(v[4] + h1.x + bb1.x, 0.f);
            r1.y = fmaxf(v[5] + h1.y + bb1.y, 0.f);
            r1.z = fmaxf(v[6] + h1.z + bb1.z, 0.f);
            r1.w = fmaxf(v[7] + h1.w + bb1.w, 0.f);
            float* op = g_h + (size_t)m * H_F + bn + tx * 8;
            *(float4*)op       = r0;
            *(float4*)(op + 4) = r1;
        }
    }
}

// ---------------- phase A: self-GEMM blocks + agg blocks, chunk-interleaved ----------------
// Chunks of SMS(=152) blocks alternate GEMM/AGG so each SM's two resident
// CTAs are one fma-bound GEMM and one mem-bound aggregation.
__global__ __launch_bounds__(256, 2) void phaseA_kernel(
    const float* __restrict__ x, const float* __restrict__ Wself,
    const void* __restrict__ src1, const void* __restrict__ dst1) {
    __shared__ float sm[SM_FLOATS];
    int bid = blockIdx.x;
    int c = bid / SMS, r = bid % SMS;
    bool gchunk = ((c & 1) == 0);
    int gidx = (c >> 1) * SMS + r;

    if (gchunk && gidx < G_GEMM1) {
        gemm1_body<0>(x, Wself, nullptr, gidx, sm);
    } else {
        int aggIdx;
        if (c & 1) aggIdx = bid - min(G_GEMM1, ((c + 1) >> 1) * SMS);
        else       aggIdx = bid - G_GEMM1;
        if (aggIdx < G_AGG1) {
            int row  = aggIdx * 8 + (threadIdx.x >> 5);
            int lane = threadIdx.x & 31;
            if (row < N_DST1) {
                if (g_is64)
                    agg1_warp<long long>(x, (const long long*)src1,
                                         (const long long*)dst1, row, lane);
                else
                    agg1_warp<int>(x, (const int*)src1, (const int*)dst1, row, lane);
            }
        }
    }
}

// ---------------- neighbor GEMM + accumulate + bias + relu ----------------
__global__ __launch_bounds__(256, 2) void neigh_gemm_kernel(
    const float* __restrict__ Wneigh, const float* __restrict__ bias1) {
    __shared__ float sm[SM_FLOATS];
    gemm1_body<1>(g_hneigh1, Wneigh, bias1, blockIdx.x, sm);
}

// ---------------- layer-2 aggregation: one warp per dst, 256 feats ----------------
template <typename IT>
__device__ __forceinline__ void agg2_warp(const IT* __restrict__ src,
                                          const IT* __restrict__ dst,
                                          int row, int lane) {
    int s, e;
    lb2(dst, E2, row, row + 1, s, e);
    float4 a0 = make_float4(0.f, 0.f, 0.f, 0.f);
    float4 a1 = make_float4(0.f, 0.f, 0.f, 0.f);
    int i = s;
    for (; i + 4 <= e; i += 4) {
        int s0 = (int)__ldg(src + i),     s1 = (int)__ldg(src + i + 1);
        int s2 = (int)__ldg(src + i + 2), s3 = (int)__ldg(src + i + 3);
        const float4* r0 = (const float4*)(g_h + (size_t)s0 * H_F);
        const float4* r1 = (const float4*)(g_h + (size_t)s1 * H_F);
        const float4* r2 = (const float4*)(g_h + (size_t)s2 * H_F);
        const float4* r3 = (const float4*)(g_h + (size_t)s3 * H_F);
        float4 u0 = r0[lane], u1 = r0[lane + 32];
        float4 w0 = r1[lane], w1 = r1[lane + 32];
        float4 p0 = r2[lane], p1 = r2[lane + 32];
        float4 q0 = r3[lane], q1 = r3[lane + 32];
        a0.x += (u0.x + w0.x) + (p0.x + q0.x); a0.y += (u0.y + w0.y) + (p0.y + q0.y);
        a0.z += (u0.z + w0.z) + (p0.z + q0.z); a0.w += (u0.w + w0.w) + (p0.w + q0.w);
        a1.x += (u1.x + w1.x) + (p1.x + q1.x); a1.y += (u1.y + w1.y) + (p1.y + q1.y);
        a1.z += (u1.z + w1.z) + (p1.z + q1.z); a1.w += (u1.w + w1.w) + (p1.w + q1.w);
    }
    for (; i < e; ++i) {
        int s0 = (int)__ldg(src + i);
        const float4* r0 = (const float4*)(g_h + (size_t)s0 * H_F);
        float4 u0 = r0[lane], u1 = r0[lane + 32];
        a0.x += u0.x; a0.y += u0.y; a0.z += u0.z; a0.w += u0.w;
        a1.x += u1.x; a1.y += u1.y; a1.z += u1.z; a1.w += u1.w;
    }
    int deg = e - s;
    float sc = 1.0f / (float)(deg > 0 ? deg : 1);
    float4* op = (float4*)(g_hneigh2 + (size_t)row * H_F);
    op[lane]      = make_float4(a0.x * sc, a0.y * sc, a0.z * sc, a0.w * sc);
    op[lane + 32] = make_float4(a1.x * sc, a1.y * sc, a1.z * sc, a1.w * sc);
}

__global__ __launch_bounds__(256) void agg2_kernel(const void* __restrict__ src2,
                                                   const void* __restrict__ dst2) {
    int gw = (blockIdx.x * 256 + threadIdx.x) >> 5;
    if (gw >= N_DST2) return;
    int lane = threadIdx.x & 31;
    if (g_is64)
        agg2_warp<long long>((const long long*)src2, (const long long*)dst2, gw, lane);
    else
        agg2_warp<int>((const int*)src2, (const int*)dst2, gw, lane);
}

// ---------------- layer-2 fused dual-GEMM + bias (no relu) ----------------
__global__ __launch_bounds__(256) void gemm2_kernel(
    const float* __restrict__ Ws2, const float* __restrict__ Wn2,
    const float* __restrict__ b2, float* __restrict__ out) {
    __shared__ float sWs[64][48];
    __shared__ float sWn[64][48];
    __shared__ float sAS[32][64];
    __shared__ float sAN[32][64];

    int t    = threadIdx.x;
    int n    = t & 63;
    int rg   = t >> 6;                      // 0..3
    int nc   = (n < N_CLS) ? n : (N_CLS - 1);
    int row0 = blockIdx.x * 32;

    float acc[8];
    #pragma unroll
    for (int i = 0; i < 8; i++) acc[i] = 0.f;

    for (int kt = 0; kt < 4; ++kt) {
        for (int idx = t; idx < 64 * N_CLS; idx += 256) {
            int kk = idx / N_CLS;
            int nn = idx - kk * N_CLS;
            sWs[kk][nn] = Ws2[(kt * 64 + kk) * N_CLS + nn];
            sWn[kk][nn] = Wn2[(kt * 64 + kk) * N_CLS + nn];
        }
        for (int idx = t; idx < 512; idx += 256) {
            int r = idx >> 4;
            int c = (idx & 15) * 4;
            *(float4*)&sAS[r][c] =
                *(const float4*)(g_h + (size_t)(row0 + r) * H_F + kt * 64 + c);
            *(float4*)&sAN[r][c] =
                *(const float4*)(g_hneigh2 + (size_t)(row0 + r) * H_F + kt * 64 + c);
        }
        __syncthreads();
        #pragma unroll 4
        for (int kk = 0; kk < 64; kk++) {
            float ws = sWs[kk][nc];
            float wn = sWn[kk][nc];
            #pragma unroll
            for (int i = 0; i < 8; i++) {
                acc[i] = fmaf(sAS[rg * 8 + i][kk], ws, acc[i]);
                acc[i] = fmaf(sAN[rg * 8 + i][kk], wn, acc[i]);
            }
        }
        __syncthreads();
    }

    if (n < N_CLS) {
        float bb = b2[n];
        #pragma unroll
        for (int i = 0; i < 8; i++) {
            int row = row0 + rg * 8 + i;
            if (row < N_DST2) out[row * N_CLS + n] = acc[i] + bb;
        }
    }
}

// ---------------- launch ----------------
extern "C" void kernel_launch(void* const* d_in, const int* in_sizes, int n_in,
                              void* d_out, int out_size) {
    const float* x       = (const float*)d_in[0];
    const float* Wself1  = (const float*)d_in[1];
    const float* Wneigh1 = (const float*)d_in[2];
    const float* b1      = (const float*)d_in[3];
    const float* Wself2  = (const float*)d_in[4];
    const float* Wneigh2 = (const float*)d_in[5];
    const float* b2      = (const float*)d_in[6];
    const void*  src1    = d_in[7];
    const void*  dst1    = d_in[8];
    const void*  src2    = d_in[9];
    const void*  dst2    = d_in[10];
    float* out = (float*)d_out;

    detect_kernel<<<1, 32>>>((const int*)src1);

    phaseA_kernel<<<G_GEMM1 + G_AGG1, 256>>>(x, Wself1, src1, dst1);

    neigh_gemm_kernel<<<G_GEMM1, 256>>>(Wneigh1, b1);

    agg2_kernel<<<(N_DST2 + 7) / 8, 256>>>(src2, dst2);

    gemm2_kernel<<<(N_DST2 + 31) / 32, 256>>>(Wself2, Wneigh2, b2, out);
}

// round 8
// speedup vs baseline: 2.1528x; 1.3463x over previous
#include <cuda_runtime.h>

// ---------------- problem constants (fixed shapes) ----------------
#define N_SRC1 200000
#define N_DST1 50000
#define N_DST2 10000
#define E1     2000000
#define E2     400000
#define IN_F   128
#define H_F    256
#define N_CLS  47

#define PAD1   50048   // N_DST1 padded to multiple of 128

// ---------------- scratch (device globals; zero-initialized) ----------------
__device__ int   g_is64;
__device__ int   g_off1[N_DST1 + 1];
__device__ int   g_off2[N_DST2 + 1];
__device__ float g_hneigh1[(size_t)PAD1 * IN_F];   // layer1 mean-aggregated feats
__device__ float g_h[(size_t)PAD1 * H_F];          // layer1 output (relu'd)
__device__ float g_hneigh2[(size_t)N_DST2 * H_F];  // layer2 mean-aggregated feats

// ---------------- index dtype detection ----------------
// src1 values are uniform-random in [0, 200000). If int64, every odd 32-bit
// word (high word) is zero; if int32, odd words are random and essentially
// surely nonzero among 128 samples.
__global__ void detect_kernel(const int* __restrict__ src1_raw) {
    if (threadIdx.x == 0) {
        int nz = 0;
        for (int i = 1; i < 256; i += 2) nz |= (src1_raw[i] != 0);
        g_is64 = nz ? 0 : 1;
    }
}

// ---------------- CSR offsets for both graphs via boundary scatter ----------------
// off[t] = lower_bound(dst, t): thread i owns all t with dst[i-1] < t <= dst[i].
__device__ __forceinline__ void scatter_one(const void* dst, int* off, int E,
                                            int ndst, int i, int is64) {
    int d, p;
    if (is64) {
        d = (int)((const long long*)dst)[i];
        p = (i == 0) ? -1 : (int)((const long long*)dst)[i - 1];
    } else {
        d = ((const int*)dst)[i];
        p = (i == 0) ? -1 : ((const int*)dst)[i - 1];
    }
    for (int t = p + 1; t <= d; ++t) off[t] = i;
    if (i == E - 1)
        for (int t = d + 1; t <= ndst; ++t) off[t] = E;
}

__global__ void offsets_kernel(const void* __restrict__ dst1,
                               const void* __restrict__ dst2) {
    int i = blockIdx.x * blockDim.x + threadIdx.x;
    int is64 = g_is64;
    if (i < E1) scatter_one(dst1, g_off1, E1, N_DST1, i, is64);
    if (i < E2) scatter_one(dst2, g_off2, E2, N_DST2, i, is64);
}

// ---------------- layer-1 aggregation: one warp per dst row, 128 feats ----------------
template <typename IT>
__global__ __launch_bounds__(256) void agg1_kernel(const float* __restrict__ x,
                                                   const IT* __restrict__ src) {
    int row = (blockIdx.x * 256 + threadIdx.x) >> 5;
    if (row >= N_DST1) return;
    int lane = threadIdx.x & 31;
    int s = g_off1[row], e = g_off1[row + 1];
    float ax = 0.f, ay = 0.f, az = 0.f, aw = 0.f;
    int i = s;
    for (; i + 4 <= e; i += 4) {            // 4 gathers in flight
        int s0 = (int)__ldg(src + i),     s1 = (int)__ldg(src + i + 1);
        int s2 = (int)__ldg(src + i + 2), s3 = (int)__ldg(src + i + 3);
        float4 v0 = __ldg((const float4*)(x + (size_t)s0 * IN_F) + lane);
        float4 v1 = __ldg((const float4*)(x + (size_t)s1 * IN_F) + lane);
        float4 v2 = __ldg((const float4*)(x + (size_t)s2 * IN_F) + lane);
        float4 v3 = __ldg((const float4*)(x + (size_t)s3 * IN_F) + lane);
        ax += (v0.x + v1.x) + (v2.x + v3.x);
        ay += (v0.y + v1.y) + (v2.y + v3.y);
        az += (v0.z + v1.z) + (v2.z + v3.z);
        aw += (v0.w + v1.w) + (v2.w + v3.w);
    }
    for (; i < e; ++i) {
        int s0 = (int)__ldg(src + i);
        float4 v0 = __ldg((const float4*)(x + (size_t)s0 * IN_F) + lane);
        ax += v0.x; ay += v0.y; az += v0.z; aw += v0.w;
    }
    int deg = e - s;
    float sc = 1.0f / (float)(deg > 0 ? deg : 1);
    ((float4*)(g_hneigh1 + (size_t)row * IN_F))[lane] =
        make_float4(ax * sc, ay * sc, az * sc, aw * sc);
}

// ---------------- layer-1 fused dual-GEMM + bias + relu ----------------
// g_h[m,n] = relu( x[m,:]@Wself[:,n] + hneigh1[m,:]@Wneigh[:,n] + b1[n] )
// K=256 concat GEMM: chunks 0..7 use (x, Wself), 8..15 use (hneigh1, Wneigh).
// BM=128 BN=128 BK=16, 256 threads, 8x8/thread, double-buffered smem,
// inner product on packed fma.rn.f32x2.
__global__ __launch_bounds__(256, 2) void gemm1_kernel(
    const float* __restrict__ x, const float* __restrict__ Wself,
    const float* __restrict__ Wneigh, const float* __restrict__ bias1) {
    __shared__ float As[2][16][136];    // transposed A tiles (k-major), padded
    __shared__ float Bs[2][16][128];

    const int bm = blockIdx.x * 128;
    const int bn = blockIdx.y * 128;
    const int tid = threadIdx.x;
    const int tx = tid & 15;            // cols bn + tx*8 .. +7
    const int ty = tid >> 4;            // rows bm + ty*8 .. +7
    const int ar = tid >> 1;            // A tile row 0..127
    const int akc = (tid & 1) * 8;      // A k-offset 0 or 8
    const int brow = tid >> 4;          // B k-row 0..15
    const int bnc = (tid & 15) * 8;     // B n-offset

    unsigned long long acc[8][4];
    #pragma unroll
    for (int i = 0; i < 8; i++)
        #pragma unroll
        for (int j = 0; j < 4; j++) acc[i][j] = 0ULL;

    // prologue: chunk 0 (x / Wself, k0 = 0) -> buf 0
    {
        const float* ap = x + (size_t)(bm + ar) * IN_F + akc;
        float4 a0 = *(const float4*)ap;
        float4 a1 = *(const float4*)(ap + 4);
        const float* wp = Wself + (size_t)brow * H_F + bn + bnc;
        float4 b0 = *(const float4*)wp;
        float4 b1 = *(const float4*)(wp + 4);
        As[0][akc + 0][ar] = a0.x; As[0][akc + 1][ar] = a0.y;
        As[0][akc + 2][ar] = a0.z; As[0][akc + 3][ar] = a0.w;
        As[0][akc + 4][ar] = a1.x; As[0][akc + 5][ar] = a1.y;
        As[0][akc + 6][ar] = a1.z; As[0][akc + 7][ar] = a1.w;
        float4* bd = (float4*)&Bs[0][brow][bnc];
        bd[0] = b0; bd[1] = b1;
    }
    __syncthreads();

    #pragma unroll 1
    for (int ch = 0; ch < 16; ++ch) {
        int buf = ch & 1;
        float4 pa0, pa1, pb0, pb1;
        if (ch < 15) {
            int chn = ch + 1;
            const float* Asel = (chn < 8) ? x : g_hneigh1;
            const float* Wsel = (chn < 8) ? Wself : Wneigh;
            int k0 = (chn & 7) * 16;
            const float* ap = Asel + (size_t)(bm + ar) * IN_F + k0 + akc;
            pa0 = *(const float4*)ap;
            pa1 = *(const float4*)(ap + 4);
            const float* wp = Wsel + (size_t)(k0 + brow) * H_F + bn + bnc;
            pb0 = *(const float4*)wp;
            pb1 = *(const float4*)(wp + 4);
        }
        #pragma unroll
        for (int k = 0; k < 16; ++k) {
            float av[8];
            #pragma unroll
            for (int i = 0; i < 8; i++) av[i] = As[buf][k][ty * 8 + i];
            const ulonglong2* bq = (const ulonglong2*)&Bs[buf][k][tx * 8];
            ulonglong2 q0 = bq[0], q1 = bq[1];
            unsigned long long bb[4] = {q0.x, q0.y, q1.x, q1.y};
            #pragma unroll
            for (int i = 0; i < 8; i++) {
                unsigned long long ad;
                asm("mov.b64 %0, {%1, %1};" : "=l"(ad) : "f"(av[i]));
                #pragma unroll
                for (int j = 0; j < 4; j++)
                    asm("fma.rn.f32x2 %0, %1, %2, %0;"
                        : "+l"(acc[i][j]) : "l"(ad), "l"(bb[j]));
            }
        }
        if (ch < 15) {
            __syncthreads();
            int nb = buf ^ 1;
            As[nb][akc + 0][ar] = pa0.x; As[nb][akc + 1][ar] = pa0.y;
            As[nb][akc + 2][ar] = pa0.z; As[nb][akc + 3][ar] = pa0.w;
            As[nb][akc + 4][ar] = pa1.x; As[nb][akc + 5][ar] = pa1.y;
            As[nb][akc + 6][ar] = pa1.z; As[nb][akc + 7][ar] = pa1.w;
            float4* bd = (float4*)&Bs[nb][brow][bnc];
            bd[0] = pb0; bd[1] = pb1;
            __syncthreads();
        }
    }

    // epilogue: bias + relu -> g_h
    float4 bb0 = *(const float4*)(bias1 + bn + tx * 8);
    float4 bb1 = *(const float4*)(bias1 + bn + tx * 8 + 4);
    #pragma unroll
    for (int i = 0; i < 8; i++) {
        int m = bm + ty * 8 + i;                  // < PAD1 always
        float v[8];
        #pragma unroll
        for (int j = 0; j < 4; j++) {
            float lo, hi;
            asm("mov.b64 {%0, %1}, %2;" : "=f"(lo), "=f"(hi) : "l"(acc[i][j]));
            v[2 * j] = lo; v[2 * j + 1] = hi;
        }
        float4 r0, r1;
        r0.x = fmaxf(v[0] + bb0.x, 0.f); r0.y = fmaxf(v[1] + bb0.y, 0.f);
        r0.z = fmaxf(v[2] + bb0.z, 0.f); r0.w = fmaxf(v[3] + bb0.w, 0.f);
        r1.x = fmaxf(v[4] + bb1.x, 0.f); r1.y = fmaxf(v[5] + bb1.y, 0.f);
        r1.z = fmaxf(v[6] + bb1.z, 0.f); r1.w = fmaxf(v[7] + bb1.w, 0.f);
        float* op = g_h + (size_t)m * H_F + bn + tx * 8;
        *(float4*)op       = r0;
        *(float4*)(op + 4) = r1;
    }
}

// ---------------- layer-2 aggregation: one warp per dst, 256 feats ----------------
template <typename IT>
__global__ __launch_bounds__(256) void agg2_kernel(const IT* __restrict__ src) {
    int row = (blockIdx.x * 256 + threadIdx.x) >> 5;
    if (row >= N_DST2) return;
    int lane = threadIdx.x & 31;
    int s = g_off2[row], e = g_off2[row + 1];
    float4 a0 = make_float4(0.f, 0.f, 0.f, 0.f);
    float4 a1 = make_float4(0.f, 0.f, 0.f, 0.f);
    int i = s;
    for (; i + 4 <= e; i += 4) {
        int s0 = (int)__ldg(src + i),     s1 = (int)__ldg(src + i + 1);
        int s2 = (int)__ldg(src + i + 2), s3 = (int)__ldg(src + i + 3);
        const float4* r0 = (const float4*)(g_h + (size_t)s0 * H_F);
        const float4* r1 = (const float4*)(g_h + (size_t)s1 * H_F);
        const float4* r2 = (const float4*)(g_h + (size_t)s2 * H_F);
        const float4* r3 = (const float4*)(g_h + (size_t)s3 * H_F);
        float4 u0 = r0[lane], u1 = r0[lane + 32];
        float4 w0 = r1[lane], w1 = r1[lane + 32];
        float4 p0 = r2[lane], p1 = r2[lane + 32];
        float4 q0 = r3[lane], q1 = r3[lane + 32];
        a0.x += (u0.x + w0.x) + (p0.x + q0.x); a0.y += (u0.y + w0.y) + (p0.y + q0.y);
        a0.z += (u0.z + w0.z) + (p0.z + q0.z); a0.w += (u0.w + w0.w) + (p0.w + q0.w);
        a1.x += (u1.x + w1.x) + (p1.x + q1.x); a1.y += (u1.y + w1.y) + (p1.y + q1.y);
        a1.z += (u1.z + w1.z) + (p1.z + q1.z); a1.w += (u1.w + w1.w) + (p1.w + q1.w);
    }
    for (; i < e; ++i) {
        int s0 = (int)__ldg(src + i);
        const float4* r0 = (const float4*)(g_h + (size_t)s0 * H_F);
        float4 u0 = r0[lane], u1 = r0[lane + 32];
        a0.x += u0.x; a0.y += u0.y; a0.z += u0.z; a0.w += u0.w;
        a1.x += u1.x; a1.y += u1.y; a1.z += u1.z; a1.w += u1.w;
    }
    int deg = e - s;
    float sc = 1.0f / (float)(deg > 0 ? deg : 1);
    float4* op = (float4*)(g_hneigh2 + (size_t)row * H_F);
    op[lane]      = make_float4(a0.x * sc, a0.y * sc, a0.z * sc, a0.w * sc);
    op[lane + 32] = make_float4(a1.x * sc, a1.y * sc, a1.z * sc, a1.w * sc);
}

// ---------------- layer-2 fused dual-GEMM + bias (no relu) ----------------
__global__ __launch_bounds__(256) void gemm2_kernel(
    const float* __restrict__ Ws2, const float* __restrict__ Wn2,
    const float* __restrict__ b2, float* __restrict__ out) {
    __shared__ float sWs[64][48];
    __shared__ float sWn[64][48];
    __shared__ float sAS[32][64];
    __shared__ float sAN[32][64];

    int t    = threadIdx.x;
    int n    = t & 63;
    int rg   = t >> 6;                      // 0..3
    int nc   = (n < N_CLS) ? n : (N_CLS - 1);
    int row0 = blockIdx.x * 32;

    float acc[8];
    #pragma unroll
    for (int i = 0; i < 8; i++) acc[i] = 0.f;

    for (int kt = 0; kt < 4; ++kt) {
        for (int idx = t; idx < 64 * N_CLS; idx += 256) {
            int kk = idx / N_CLS;
            int nn = idx - kk * N_CLS;
            sWs[kk][nn] = Ws2[(kt * 64 + kk) * N_CLS + nn];
            sWn[kk][nn] = Wn2[(kt * 64 + kk) * N_CLS + nn];
        }
        for (int idx = t; idx < 512; idx += 256) {
            int r = idx >> 4;
            int c = (idx & 15) * 4;
            *(float4*)&sAS[r][c] =
                *(const float4*)(g_h + (size_t)(row0 + r) * H_F + kt * 64 + c);
            *(float4*)&sAN[r][c] =
                *(const float4*)(g_hneigh2 + (size_t)(row0 + r) * H_F + kt * 64 + c);
        }
        __syncthreads();
        #pragma unroll 4
        for (int kk = 0; kk < 64; kk++) {
            float ws = sWs[kk][nc];
            float wn = sWn[kk][nc];
            #pragma unroll
            for (int i = 0; i < 8; i++) {
                acc[i] = fmaf(sAS[rg * 8 + i][kk], ws, acc[i]);
                acc[i] = fmaf(sAN[rg * 8 + i][kk], wn, acc[i]);
            }
        }
        __syncthreads();
    }

    if (n < N_CLS) {
        float bb = b2[n];
        #pragma unroll
        for (int i = 0; i < 8; i++) {
            int row = row0 + rg * 8 + i;
            if (row < N_DST2) out[row * N_CLS + n] = acc[i] + bb;
        }
    }
}

// ---------------- dispatchers for raw-index agg kernels ----------------
__global__ void null_kernel() {}

// ---------------- launch ----------------
extern "C" void kernel_launch(void* const* d_in, const int* in_sizes, int n_in,
                              void* d_out, int out_size) {
    const float* x       = (const float*)d_in[0];
    const float* Wself1  = (const float*)d_in[1];
    const float* Wneigh1 = (const float*)d_in[2];
    const float* b1      = (const float*)d_in[3];
    const float* Wself2  = (const float*)d_in[4];
    const float* Wneigh2 = (const float*)d_in[5];
    const float* b2      = (const float*)d_in[6];
    const void*  src1    = d_in[7];
    const void*  dst1    = d_in[8];
    const void*  src2    = d_in[9];
    const void*  dst2    = d_in[10];
    float* out = (float*)d_out;

    // index width is a property of the input buffers: decide on HOST from the
    // element-count metadata (in_sizes counts elements, not bytes, so it can't
    // disambiguate) -> use device-side detection + templated kernels, picking
    // the template instantiation via a tiny device flag read... but graph
    // capture must record fixed launches, so launch BOTH template variants;
    // each checks g_is64 first and exits if it doesn't match.
    detect_kernel<<<1, 32>>>((const int*)src1);
    offsets_kernel<<<(E1 + 255) / 256, 256>>>(dst1, dst2);

    // agg1: both variants launched; the wrong-width one self-disables.
    agg1_guard_launch:
    {
        // int32 variant
        extern __global__ void agg1_i32_entry(const float*, const int*);
        extern __global__ void agg1_i64_entry(const float*, const long long*);
    }
    // (see wrappers below)
    void agg1_i32_launch(const float*, const void*);
    void agg1_i64_launch(const float*, const void*);

    // -- actual launches via guarded wrappers defined after this function --
    extern void launch_rest(const float*, const float*, const float*, const float*,
                            const float*, const float*, const float*,
                            const void*, const void*, float*);
    launch_rest(x, Wself1, Wneigh1, b1, Wself2, Wneigh2, b2, src1, src2, out);
}

// ---- guarded agg wrappers: each checks g_is64 and no-ops on mismatch ----
template <typename IT, int WANT64>
__global__ __launch_bounds__(256) void agg1_guarded(const float* __restrict__ x,
                                                    const void* __restrict__ srcv) {
    if (g_is64 != WANT64) return;
    const IT* src = (const IT*)srcv;
    int row = (blockIdx.x * 256 + threadIdx.x) >> 5;
    if (row >= N_DST1) return;
    int lane = threadIdx.x & 31;
    int s = g_off1[row], e = g_off1[row + 1];
    float ax = 0.f, ay = 0.f, az = 0.f, aw = 0.f;
    int i = s;
    for (; i + 4 <= e; i += 4) {
        int s0 = (int)__ldg(src + i),     s1 = (int)__ldg(src + i + 1);
        int s2 = (int)__ldg(src + i + 2), s3 = (int)__ldg(src + i + 3);
        float4 v0 = __ldg((const float4*)(x + (size_t)s0 * IN_F) + lane);
        float4 v1 = __ldg((const float4*)(x + (size_t)s1 * IN_F) + lane);
        float4 v2 = __ldg((const float4*)(x + (size_t)s2 * IN_F) + lane);
        float4 v3 = __ldg((const float4*)(x + (size_t)s3 * IN_F) + lane);
        ax += (v0.x + v1.x) + (v2.x + v3.x);
        ay += (v0.y + v1.y) + (v2.y + v3.y);
        az += (v0.z + v1.z) + (v2.z + v3.z);
        aw += (v0.w + v1.w) + (v2.w + v3.w);
    }
    for (; i < e; ++i) {
        int s0 = (int)__ldg(src + i);
        float4 v0 = __ldg((const float4*)(x + (size_t)s0 * IN_F) + lane);
        ax += v0.x; ay += v0.y; az += v0.z; aw += v0.w;
    }
    int deg = e - s;
    float sc = 1.0f / (float)(deg > 0 ? deg : 1);
    ((float4*)(g_hneigh1 + (size_t)row * IN_F))[lane] =
        make_float4(ax * sc, ay * sc, az * sc, aw * sc);
}

template <typename IT, int WANT64>
__global__ __launch_bounds__(256) void agg2_guarded(const void* __restrict__ srcv) {
    if (g_is64 != WANT64) return;
    const IT* src = (const IT*)srcv;
    int row = (blockIdx.x * 256 + threadIdx.x) >> 5;
    if (row >= N_DST2) return;
    int lane = threadIdx.x & 31;
    int s = g_off2[row], e = g_off2[row + 1];
    float4 a0 = make_float4(0.f, 0.f, 0.f, 0.f);
    float4 a1 = make_float4(0.f, 0.f, 0.f, 0.f);
    int i = s;
    for (; i + 4 <= e; i += 4) {
        int s0 = (int)__ldg(src + i),     s1 = (int)__ldg(src + i + 1);
        int s2 = (int)__ldg(src + i + 2), s3 = (int)__ldg(src + i + 3);
        const float4* r0 = (const float4*)(g_h + (size_t)s0 * H_F);
        const float4* r1 = (const float4*)(g_h + (size_t)s1 * H_F);
        const float4* r2 = (const float4*)(g_h + (size_t)s2 * H_F);
        const float4* r3 = (const float4*)(g_h + (size_t)s3 * H_F);
        float4 u0 = r0[lane], u1 = r0[lane + 32];
        float4 w0 = r1[lane], w1 = r1[lane + 32];
        float4 p0 = r2[lane], p1 = r2[lane + 32];
        float4 q0 = r3[lane], q1 = r3[lane + 32];
        a0.x += (u0.x + w0.x) + (p0.x + q0.x); a0.y += (u0.y + w0.y) + (p0.y + q0.y);
        a0.z += (u0.z + w0.z) + (p0.z + q0.z); a0.w += (u0.w + w0.w) + (p0.w + q0.w);
        a1.x += (u1.x + w1.x) + (p1.x + q1.x); a1.y += (u1.y + w1.y) + (p1.y + q1.y);
        a1.z += (u1.z + w1.z) + (p1.z + q1.z); a1.w += (u1.w + w1.w) + (p1.w + q1.w);
    }
    for (; i < e; ++i) {
        int s0 = (int)__ldg(src + i);
        const float4* r0 = (const float4*)(g_h + (size_t)s0 * H_F);
        float4 u0 = r0[lane], u1 = r0[lane + 32];
        a0.x += u0.x; a0.y += u0.y; a0.z += u0.z; a0.w += u0.w;
        a1.x += u1.x; a1.y += u1.y; a1.z += u1.z; a1.w += u1.w;
    }
    int deg = e - s;
    float sc = 1.0f / (float)(deg > 0 ? deg : 1);
    float4* op = (float4*)(g_hneigh2 + (size_t)row * H_F);
    op[lane]      = make_float4(a0.x * sc, a0.y * sc, a0.z * sc, a0.w * sc);
    op[lane + 32] = make_float4(a1.x * sc, a1.y * sc, a1.z * sc, a1.w * sc);
}

void launch_rest(const float* x, const float* Wself1, const float* Wneigh1,
                 const float* b1, const float* Wself2, const float* Wneigh2,
                 const float* b2, const void* src1, const void* src2, float* out) {
    // agg1 (both width variants; wrong one exits immediately)
    agg1_guarded<int, 0><<<(N_DST1 + 7) / 8, 256>>>(x, src1);
    agg1_guarded<long long, 1><<<(N_DST1 + 7) / 8, 256>>>(x, src1);

    dim3 g1(PAD1 / 128, 2);
    gemm1_kernel<<<g1, 256>>>(x, Wself1, Wneigh1, b1);

    agg2_guarded<int, 0><<<(N_DST2 + 7) / 8, 256>>>(src2);
    agg2_guarded<long long, 1><<<(N_DST2 + 7) / 8, 256>>>(src2);

    gemm2_kernel<<<(N_DST2 + 31) / 32, 256>>>(Wself2, Wneigh2, b2, out);
}